// round 11
// baseline (speedup 1.0000x reference)
#include <cuda_runtime.h>
#include <cuda_fp16.h>
#include <cstdint>
#include <cstring>

// Problem dims
#define FIN   4096
#define FOUT  4096
#define MTOT  4096   // 2 * 2048

#define KCHUNKS 64          // K chunks of 64
#define NSTAGE  4
#define A_BYTES      16384  // 128 rows x 128B (this CTA's M-half)
#define BH_BYTES     16384  // one B half: 128 rows x 128B
#define STAGE_BYTES  49152  // A + B0half + B1half
#define TX_BYTES     49152  // per-CTA TMA bytes per stage

// SMEM layout (dynamic):
//   [0..4)     TMEM base ptr (written by tcgen05.alloc cg2)
//   [8..72)    full[s]=8+16s, empty[s]=16+16s  (s=0..3)
//   [72..80)   done mbarrier
//   [1024 + s*49152) stage s: A(16K) | B0half(16K) | B1half(16K)
#define SM_BAR    8
#define SM_DONE   72
#define SM_TILE0  1024
#define SMEM_BYTES (1024 + NSTAGE * STAGE_BYTES)   // 197632, occupancy 1

// idesc kind::f16 cg2: dtype=F32(1<<4), a/b=F16(0), N=256 -> 32<<17,
// M=256 -> 16<<24
#define IDESC_CG2 0x10400010u
// cluster rank bit in SMEM addresses (Sm100MmaPeerBitMask)
#define PEER_MASK 0xFEFFFFFFu

#if defined(__CUDA_ARCH__) && \
    (defined(__CUDA_ARCH_FEAT_SM103_ALL) || defined(__CUDA_ARCH_FEAT_SM100_ALL) || \
     defined(__CUDA_ARCH_FEAT_SM101_ALL))
#define HAS_TCGEN05 1
#else
#define HAS_TCGEN05 0
#endif

// fp16 staging in chunk-blocked, pre-SW128-swizzled layout:
// g_A: [mtile(32 x 128rows)][chunk(64)][16384B]
// g_B: [ntile(16 x 256rows)][chunk(64)][32768B]; each 16KB half-block is a
//      standalone SW128 128-row image (swizzle is row-local).
__device__ __half g_A[(size_t)MTOT * FIN];
__device__ __half g_B[(size_t)FOUT * FIN];

// per-k-chunk readiness counters (prep -> gemm). A target: 128, B target: 64.
__device__ unsigned int g_rdyA[KCHUNKS];
__device__ unsigned int g_rdyB[KCHUNKS];

#define PREP_ITEMS (KCHUNKS * 192)   // per chunk: 128 cvt items + 64 xform items

#define SWZ(x) ((x) ^ (((x) >> 3) & 0x70))

__device__ __forceinline__ uint32_t h2u(__half2 h) {
    uint32_t u; memcpy(&u, &h, 4); return u;
}

__device__ __forceinline__ uint32_t smem_u32(const void* p) {
    uint32_t a;
    asm("{ .reg .u64 t; cvta.to.shared.u64 t, %1; cvt.u32.u64 %0, t; }"
        : "=r"(a) : "l"(p));
    return a;
}

// acquire-poll a global counter until it reaches tgt
__device__ __forceinline__ void wait_flag(const unsigned int* p, unsigned int tgt) {
    unsigned int v;
    while (true) {
        asm volatile("ld.acquire.gpu.global.b32 %0, [%1];"
                     : "=r"(v) : "l"(p) : "memory");
        if (v >= tgt) return;
        __nanosleep(64);
    }
}

#if HAS_TCGEN05
__device__ __forceinline__ bool elect_one() {
    uint32_t pred;
    asm volatile(
        "{\n\t.reg .pred p;\n\t"
        "elect.sync _|p, 0xFFFFFFFF;\n\t"
        "selp.b32 %0, 1, 0, p;\n\t}"
        : "=r"(pred));
    return pred != 0;
}

// SW128 K-major smem descriptor: layout=SW128(2), version=1, SBO=64, LBO=1
static constexpr unsigned long long DESC_BASE =
    (2ULL << 61) | (1ULL << 46) | (64ULL << 32) | (1ULL << 16);

__device__ __forceinline__ uint64_t make_desc(uint32_t addr) {
    return DESC_BASE | ((uint64_t)(addr >> 4) & 0x3FFF);
}

__device__ __forceinline__ void wait_parity(uint32_t mbar, int phase) {
    asm volatile(
        "{\n\t.reg .pred P;\n\t"
        "WL%=:\n\t"
        "mbarrier.try_wait.parity.acquire.cta.shared::cta.b64 P, [%0], %1, 0x989680;\n\t"
        "@P bra.uni WD%=;\n\t"
        "bra.uni WL%=;\n\t"
        "WD%=:\n\t}"
        :: "r"(mbar), "r"((uint32_t)phase) : "memory");
}

__device__ __forceinline__ void bulk_g2s(uint32_t dst, const void* src,
                                         uint32_t bytes, uint32_t mbar) {
    asm volatile(
        "cp.async.bulk.shared::cluster.global.mbarrier::complete_tx::bytes "
        "[%0], [%1], %2, [%3];"
        :: "r"(dst), "l"(src), "r"(bytes), "r"(mbar) : "memory");
}

__device__ __forceinline__ void mma_f16_ss_cg2(uint32_t d_tmem, uint64_t a_desc,
                                               uint64_t b_desc, uint32_t en) {
    asm volatile(
        "{\n\t.reg .pred p;\n\t"
        "setp.ne.u32 p, %5, 0;\n\t"
        "tcgen05.mma.cta_group::2.kind::f16 [%0], %1, %2, %3, "
        "{%4, %4, %4, %4, %4, %4, %4, %4}, p;\n\t}"
        :: "r"(d_tmem), "l"(a_desc), "l"(b_desc), "r"(IDESC_CG2),
           "r"(0u), "r"(en)
        : "memory");
}

__device__ __forceinline__ void ldtm_x32(uint32_t* r, uint32_t tmem_addr) {
    asm volatile(
        "tcgen05.ld.sync.aligned.32x32b.x32.b32 "
        "{%0, %1, %2, %3, %4, %5, %6, %7, "
        " %8, %9, %10, %11, %12, %13, %14, %15, "
        " %16, %17, %18, %19, %20, %21, %22, %23, "
        " %24, %25, %26, %27, %28, %29, %30, %31}, [%32];"
        : "=r"(r[0]),  "=r"(r[1]),  "=r"(r[2]),  "=r"(r[3]),
          "=r"(r[4]),  "=r"(r[5]),  "=r"(r[6]),  "=r"(r[7]),
          "=r"(r[8]),  "=r"(r[9]),  "=r"(r[10]), "=r"(r[11]),
          "=r"(r[12]), "=r"(r[13]), "=r"(r[14]), "=r"(r[15]),
          "=r"(r[16]), "=r"(r[17]), "=r"(r[18]), "=r"(r[19]),
          "=r"(r[20]), "=r"(r[21]), "=r"(r[22]), "=r"(r[23]),
          "=r"(r[24]), "=r"(r[25]), "=r"(r[26]), "=r"(r[27]),
          "=r"(r[28]), "=r"(r[29]), "=r"(r[30]), "=r"(r[31])
        : "r"(tmem_addr));
}
#endif  // HAS_TCGEN05

// ---------------------------------------------------------------------------
// Kernel 0: re-arm chunk-ready counters (runs every graph replay).
// ---------------------------------------------------------------------------
__global__ void zero_flags() {
    if (threadIdx.x < KCHUNKS) {
        g_rdyA[threadIdx.x] = 0;
        g_rdyB[threadIdx.x] = 0;
    }
}

// ---------------------------------------------------------------------------
// Kernel 1: persistent fused transform, k-chunk-ordered items.
// item = c*192 + sub; sub<128: cvt (32 rows x 8 kvecs of chunk c);
// sub>=128: weight xform (64 rows x 64 cols of chunk c).
// All CTAs resident in wave 1 -> PDL trigger fires immediately -> the GEMM
// launches and consumes chunks as counters reach their targets.
// ---------------------------------------------------------------------------
__global__ void __launch_bounds__(256, 3) prep_kernel(
    const float4* __restrict__ in, const float* __restrict__ W,
    const float* __restrict__ cw, const float* __restrict__ cb,
    const float* __restrict__ sk) {
#if defined(__CUDA_ARCH__) && __CUDA_ARCH__ >= 900
    cudaTriggerProgrammaticLaunchCompletion();
#endif
    int tid = threadIdx.x;
    for (int item = blockIdx.x; item < PREP_ITEMS; item += gridDim.x) {
        int c = item / 192, sub = item - c * 192;
        if (sub < 128) {
            // ---- cvt: rows sub*32..+32, kvecs c*8..+8 of inp -> g_A ----
            int m = sub * 32 + (tid >> 3), v = tid & 7, kv = c * 8 + v;
            float4 v0 = in[(size_t)m * 1024 + kv * 2];
            float4 v1 = in[(size_t)m * 1024 + kv * 2 + 1];
            uint4 u;
            u.x = h2u(__floats2half2_rn(v0.x, v0.y));
            u.y = h2u(__floats2half2_rn(v0.z, v0.w));
            u.z = h2u(__floats2half2_rn(v1.x, v1.y));
            u.w = h2u(__floats2half2_rn(v1.z, v1.w));
            uint32_t blk = (uint32_t)(m >> 7) * 64 + c;
            uint32_t off = SWZ((uint32_t)(m & 127) * 128 + v * 16);
            *reinterpret_cast<uint4*>(reinterpret_cast<char*>(g_A) +
                                      (size_t)blk * A_BYTES + off) = u;
            __threadfence();
            __syncthreads();
            if (tid == 0) atomicAdd(&g_rdyA[c], 1u);
        } else {
            // ---- xform: rows (sub-128)*64..+64, cols c*64..+64 of W -> g_B ----
            int rb = sub - 128;
            int row = rb * 64 + (tid >> 2), q = tid & 3;
            int cc = c * 64 + q * 16;
            int h = row >> 10, r = row & 1023;

            float kk[9];
#pragma unroll
            for (int j = 0; j < 9; ++j) kk[j] = cw[h * 9 + j];
            float bias = cb[h];
            float gate = 1.0f / (1.0f + expf(-sk[h]));

            float acc[16], cen[16];
#pragma unroll
            for (int j = 0; j < 16; ++j) acc[j] = bias;

            const float* base = W + (size_t)(h << 10) * FIN;
#pragma unroll
            for (int dr = -1; dr <= 1; ++dr) {
                int rr = r + dr;
                if (rr < 0 || rr > 1023) continue;
                const float* rp = base + (size_t)rr * FIN;
                float w[18];
                w[0] = (cc > 0) ? rp[cc - 1] : 0.f;
#pragma unroll
                for (int g = 0; g < 4; ++g) {
                    float4 t = *reinterpret_cast<const float4*>(rp + cc + g * 4);
                    w[1 + g * 4] = t.x; w[2 + g * 4] = t.y;
                    w[3 + g * 4] = t.z; w[4 + g * 4] = t.w;
                }
                w[17] = (cc + 16 < FIN) ? rp[cc + 16] : 0.f;
                if (dr == 0) {
#pragma unroll
                    for (int j = 0; j < 16; ++j) cen[j] = w[j + 1];
                }
                int kr = (dr + 1) * 3;
#pragma unroll
                for (int j = 0; j < 16; ++j)
                    acc[j] += kk[kr] * w[j] + kk[kr + 1] * w[j + 1] +
                              kk[kr + 2] * w[j + 2];
            }

            uint32_t blk = (uint32_t)(row >> 8) * 64 + c;
            int kv0 = q * 2;   // (kv & 7) for the two output vectors
#pragma unroll
            for (int half = 0; half < 2; ++half) {
                uint4 u;
                int b = half * 8;
                u.x = h2u(__floats2half2_rn(acc[b+0] + gate * cen[b+0],
                                            acc[b+1] + gate * cen[b+1]));
                u.y = h2u(__floats2half2_rn(acc[b+2] + gate * cen[b+2],
                                            acc[b+3] + gate * cen[b+3]));
                u.z = h2u(__floats2half2_rn(acc[b+4] + gate * cen[b+4],
                                            acc[b+5] + gate * cen[b+5]));
                u.w = h2u(__floats2half2_rn(acc[b+6] + gate * cen[b+6],
                                            acc[b+7] + gate * cen[b+7]));
                uint32_t off = SWZ((uint32_t)(row & 255) * 128 + (kv0 + half) * 16);
                *reinterpret_cast<uint4*>(reinterpret_cast<char*>(g_B) +
                                          (size_t)blk * 32768 + off) = u;
            }
            __threadfence();
            __syncthreads();
            if (tid == 0) atomicAdd(&g_rdyB[c], 1u);
        }
    }
}

// ---------------------------------------------------------------------------
// Kernel 2: cg2 tcgen05 GEMM (identical structure to R10) + per-chunk
// readiness polling so it can run concurrently with prep_kernel under PDL.
// CTA-pair computes 256(M) x 512(N); fp32 accumulate in TMEM (512 cols).
// ---------------------------------------------------------------------------
__global__ void __launch_bounds__(256, 1) __cluster_dims__(2, 1, 1)
gemm_kernel(float* __restrict__ out) {
    extern __shared__ char smem[];
    int tid = threadIdx.x;
    int pn = blockIdx.x >> 1;        // 8 n-pairs (512 cols each)
    int rank = blockIdx.x & 1;       // cg2 pair rank
    int pm = blockIdx.y;             // 16 m-pairs (256 rows each)

#if HAS_TCGEN05
    uint32_t sb = smem_u32(smem);
    int wid = tid >> 5, lid = tid & 31;

    if (tid == 0) {
#pragma unroll
        for (int s = 0; s < NSTAGE; ++s) {
            // leader full: expect_tx arrive + follower relay arrive = 2
            asm volatile("mbarrier.init.shared.b64 [%0], %1;"
                         :: "r"(sb + SM_BAR + s * 16),
                            "r"(rank == 0 ? 2u : 1u) : "memory");
            asm volatile("mbarrier.init.shared.b64 [%0], 1;"
                         :: "r"(sb + SM_BAR + s * 16 + 8) : "memory");   // empty
        }
        asm volatile("mbarrier.init.shared.b64 [%0], 1;"
                     :: "r"(sb + SM_DONE) : "memory");
    }
    if (wid == 0) {
        asm volatile("tcgen05.alloc.cta_group::2.sync.aligned.shared::cta.b32 [%0], 512;"
                     :: "r"(sb) : "memory");
        asm volatile("tcgen05.relinquish_alloc_permit.cta_group::2.sync.aligned;");
    }
    __syncthreads();
    // pair barriers must exist before any cross-CTA arrive / commit multicast
    asm volatile("barrier.cluster.arrive.aligned;" ::: "memory");
    asm volatile("barrier.cluster.wait.aligned;" ::: "memory");

    uint32_t tmem;
    asm volatile("ld.shared.b32 %0, [%1];" : "=r"(tmem) : "r"(sb));

    if (wid == 0 && elect_one()) {
        // ---- producer (both ranks): stage own A-half + own two B-splits ----
        const char* gAp = reinterpret_cast<const char*>(g_A) +
                          (size_t)(pm * 2 + rank) * 64 * A_BYTES;
        const char* gB0 = reinterpret_cast<const char*>(g_B) +
                          (size_t)(pn * 2) * 64 * 32768 + (size_t)rank * 16384;
        const char* gB1 = reinterpret_cast<const char*>(g_B) +
                          (size_t)(pn * 2 + 1) * 64 * 32768 + (size_t)rank * 16384;
        int eph[NSTAGE] = {0, 0, 0, 0};
        for (int i = 0; i < KCHUNKS; ++i) {
            int s = i & (NSTAGE - 1);
            uint32_t full = sb + SM_BAR + s * 16;
            if (i >= NSTAGE) { wait_parity(full + 8, eph[s]); eph[s] ^= 1; }
            // chunk i produced? (prep_kernel runs concurrently under PDL)
            wait_flag(&g_rdyA[i], 128u);
            wait_flag(&g_rdyB[i], 64u);
            asm volatile("mbarrier.arrive.expect_tx.shared.b64 _, [%0], %1;"
                         :: "r"(full), "r"((uint32_t)TX_BYTES) : "memory");
            uint32_t dst = sb + SM_TILE0 + s * STAGE_BYTES;
            bulk_g2s(dst,         gAp + (size_t)i * A_BYTES, A_BYTES, full);
            bulk_g2s(dst + 16384, gB0 + (size_t)i * 32768, BH_BYTES, full);
            bulk_g2s(dst + 32768, gB1 + (size_t)i * 32768, BH_BYTES, full);
        }
    } else if (wid == 1 && elect_one()) {
        if (rank == 0) {
            // ---- consumer (leader): 8 cg2 MMAs per chunk ----
            int fph[NSTAGE] = {0, 0, 0, 0};
            for (int i = 0; i < KCHUNKS; ++i) {
                int s = i & (NSTAGE - 1);
                uint32_t full = sb + SM_BAR + s * 16;
                wait_parity(full, fph[s]); fph[s] ^= 1;
                uint32_t sA = sb + SM_TILE0 + s * STAGE_BYTES;
                uint64_t ad  = make_desc(sA);
                uint64_t bd0 = make_desc(sA + 16384);
                uint64_t bd1 = make_desc(sA + 32768);
#pragma unroll
                for (int ks = 0; ks < 4; ++ks) {   // K=16 steps; +32B per step
                    uint32_t en = (uint32_t)(i | ks);
                    mma_f16_ss_cg2(tmem,       ad + ks * 2, bd0 + ks * 2, en);
                    mma_f16_ss_cg2(tmem + 256, ad + ks * 2, bd1 + ks * 2, en);
                }
                if (i < KCHUNKS - 1) {
                    asm volatile(
                        "tcgen05.commit.cta_group::2.mbarrier::arrive::one."
                        "shared::cluster.multicast::cluster.b64 [%0], %1;"
                        :: "r"(full + 8), "h"((uint16_t)0x3) : "memory");
                } else {
                    asm volatile(
                        "tcgen05.commit.cta_group::2.mbarrier::arrive::one."
                        "shared::cluster.multicast::cluster.b64 [%0], %1;"
                        :: "r"(sb + SM_DONE), "h"((uint16_t)0x3) : "memory");
                }
            }
        } else {
            // ---- relay (follower): own data ready -> arrive leader's full ----
            int fph[NSTAGE] = {0, 0, 0, 0};
            for (int i = 0; i < KCHUNKS; ++i) {
                int s = i & (NSTAGE - 1);
                uint32_t full = sb + SM_BAR + s * 16;
                wait_parity(full, fph[s]); fph[s] ^= 1;
                asm volatile("mbarrier.arrive.shared::cluster.b64 _, [%0];"
                             :: "r"(full & PEER_MASK) : "memory");
            }
        }
    }

    // all warps (both CTAs): wait for full accumulation
    wait_parity(sb + SM_DONE, 0);
    asm volatile("tcgen05.fence::after_thread_sync;" ::: "memory");
    __syncthreads();

    // Epilogue: rows pm*256 + rank*128 .. +128, cols pn*512 .. +512.
    int sp = wid & 3, halfc = wid >> 2;
    float* scr = reinterpret_cast<float*>(smem + 1024 + wid * 4224);  // 32x33 f32
    int rowb = pm * 256 + rank * 128 + sp * 32;
    int col0 = pn * 512 + halfc * 256;
#pragma unroll 1
    for (int cb = 0; cb < 8; ++cb) {
        uint32_t regs[32];
        uint32_t ta = tmem + (uint32_t)(halfc * 256 + cb * 32) + ((uint32_t)sp << 21);
        ldtm_x32(regs, ta);
        asm volatile("tcgen05.wait::ld.sync.aligned;" ::: "memory");
#pragma unroll
        for (int j = 0; j < 32; ++j) scr[lid * 33 + j] = __uint_as_float(regs[j]);
        __syncwarp();
#pragma unroll 4
        for (int r2 = 0; r2 < 32; ++r2)
            out[(size_t)(rowb + r2) * FOUT + col0 + cb * 32 + lid] = scr[r2 * 33 + lid];
        __syncwarp();
    }
    asm volatile("tcgen05.fence::before_thread_sync;" ::: "memory");
    __syncthreads();
    if (wid == 0) {
        asm volatile("tcgen05.dealloc.cta_group::2.sync.aligned.b32 %0, 512;" :: "r"(tmem));
    }
    // no CTA exits while peer commits/arrives could still target it
    asm volatile("barrier.cluster.arrive.aligned;" ::: "memory");
    asm volatile("barrier.cluster.wait.aligned;" ::: "memory");

#else  // ---------- FFMA fallback (plain sm_103 pass; correctness safety net) ----
    __half* tA = reinterpret_cast<__half*>(smem + SM_TILE0);            // 128x64
    __half* tB = reinterpret_cast<__half*>(smem + SM_TILE0 + 16384);    // 256x64
    int tm = tid >> 4, tn = tid & 15;
    int mt = pm * 2 + rank;
    int m0f = mt << 7;

    const uint4* gA4 = reinterpret_cast<const uint4*>(g_A);
    const uint4* gB4 = reinterpret_cast<const uint4*>(g_B);

    for (int qn = 0; qn < 2; ++qn) {
        int nt = pn * 2 + qn;
        int n0f = nt << 8;
        float acc[8][16];
#pragma unroll
        for (int r = 0; r < 8; ++r)
#pragma unroll
            for (int c = 0; c < 16; ++c) acc[r][c] = 0.f;

        for (int i = 0; i < KCHUNKS; ++i) {
            if (tid == 0) { wait_flag(&g_rdyA[i], 128u); wait_flag(&g_rdyB[i], 64u); }
            __syncthreads();
            uint32_t blkA = (uint32_t)mt * 64 + i;
            uint32_t blkB = (uint32_t)nt * 64 + i;
#pragma unroll
            for (int it = 0; it < 4; ++it) {
                int t = tid + it * 256;
                int r = t >> 3, v = t & 7;
                reinterpret_cast<uint4*>(tA)[r * 8 + v] =
                    gA4[(size_t)blkA * 1024 + (SWZ((uint32_t)(r * 128 + v * 16)) >> 4)];
            }
#pragma unroll
            for (int it = 0; it < 8; ++it) {
                int t = tid + it * 256;
                int r = t >> 3, v = t & 7;
                reinterpret_cast<uint4*>(tB)[r * 8 + v] =
                    gB4[(size_t)blkB * 2048 + (SWZ((uint32_t)(r * 128 + v * 16)) >> 4)];
            }
            __syncthreads();

            for (int k = 0; k < 64; ++k) {
                float av[8], bv[16];
#pragma unroll
                for (int r = 0; r < 8; ++r) av[r] = __half2float(tA[(tm * 8 + r) * 64 + k]);
#pragma unroll
                for (int c = 0; c < 16; ++c) bv[c] = __half2float(tB[(tn * 16 + c) * 64 + k]);
#pragma unroll
                for (int r = 0; r < 8; ++r)
#pragma unroll
                    for (int c = 0; c < 16; ++c) acc[r][c] += av[r] * bv[c];
            }
            __syncthreads();
        }
#pragma unroll
        for (int r = 0; r < 8; ++r)
#pragma unroll
            for (int c = 0; c < 16; ++c)
                out[(size_t)(m0f + tm * 8 + r) * FOUT + n0f + tn * 16 + c] = acc[r][c];
        __syncthreads();
    }
#endif
}

// ---------------------------------------------------------------------------
extern "C" void kernel_launch(void* const* d_in, const int* in_sizes, int n_in,
                              void* d_out, int out_size) {
    const float* inp = (const float*)d_in[0];  // [2, 2048, 4096]
    const float* W   = (const float*)d_in[1];  // [4096, 4096]
    const float* cw  = (const float*)d_in[2];  // [4, 1, 3, 3]
    const float* cb  = (const float*)d_in[3];  // [4]
    const float* sk  = (const float*)d_in[4];  // [4, 1, 1]
    float* out = (float*)d_out;                // [2, 2048, 4096]

    cudaFuncSetAttribute(gemm_kernel,
                         cudaFuncAttributeMaxDynamicSharedMemorySize, SMEM_BYTES);

    zero_flags<<<1, 64>>>();
    prep_kernel<<<444, 256>>>((const float4*)inp, W, cw, cb, sk);

    // GEMM with programmatic dependent launch: starts while prep is running;
    // per-chunk flags gate the actual data consumption.
    cudaLaunchConfig_t cfg = {};
    cfg.gridDim = dim3(16, 16, 1);
    cfg.blockDim = dim3(256, 1, 1);
    cfg.dynamicSmemBytes = SMEM_BYTES;
    cfg.stream = 0;
    cudaLaunchAttribute at[1];
    at[0].id = cudaLaunchAttributeProgrammaticStreamSerialization;
    at[0].val.programmaticStreamSerializationAllowed = 1;
    cfg.attrs = at;
    cfg.numAttrs = 1;
    cudaError_t e = cudaLaunchKernelEx(&cfg, gemm_kernel, out);
    if (e != cudaSuccess) {
        // PDL unavailable: plain serialized launch (still correct; flags
        // are already satisfied when the GEMM starts).
        gemm_kernel<<<dim3(16, 16), 256, SMEM_BYTES>>>(out);
    }
}

// round 12
// speedup vs baseline: 1.1261x; 1.1261x over previous
#include <cuda_runtime.h>
#include <cuda_fp16.h>
#include <cstdint>
#include <cstring>

// Problem dims
#define FIN   4096
#define FOUT  4096
#define MTOT  4096   // 2 * 2048

#define KCHUNKS 64          // K chunks of 64
#define NSTAGE  4
#define A_BYTES      16384  // 128 rows x 128B (this CTA's M-half)
#define BH_BYTES     16384  // one B half: 128 rows x 128B
#define STAGE_BYTES  49152  // A + B0half + B1half
#define TX_BYTES     49152  // per-CTA TMA bytes per stage

// SMEM layout (dynamic):
//   [0..4)     TMEM base ptr (written by tcgen05.alloc cg2)
//   [8..72)    full[s]=8+16s, empty[s]=16+16s  (s=0..3)
//   [72..80)   done mbarrier
//   [1024 + s*49152) stage s: A(16K) | B0half(16K) | B1half(16K)
#define SM_BAR    8
#define SM_DONE   72
#define SM_TILE0  1024
#define SMEM_BYTES (1024 + NSTAGE * STAGE_BYTES)   // 197632, occupancy 1

// idesc kind::f16 cg2: dtype=F32(1<<4), a/b=F16(0), N=256 -> 32<<17,
// M=256 -> 16<<24
#define IDESC_CG2 0x10400010u
#define PEER_MASK 0xFEFFFFFFu

// prep work decomposition: 4 quarters x (1024 cvt blocks + 2048 xform blocks)
#define QBLOCKS    3072
#define PREP_ITEMS (4 * QBLOCKS)
#define PREP_GRID  592           // 4 CTAs/SM -> all resident wave 1
#define GEMM_CTAS  256

#if defined(__CUDA_ARCH__) && \
    (defined(__CUDA_ARCH_FEAT_SM103_ALL) || defined(__CUDA_ARCH_FEAT_SM100_ALL) || \
     defined(__CUDA_ARCH_FEAT_SM101_ALL))
#define HAS_TCGEN05 1
#else
#define HAS_TCGEN05 0
#endif

// fp16 staging in chunk-blocked, pre-SW128-swizzled layout:
// g_A: [mtile(32 x 128rows)][chunk(64)][16384B]
// g_B: [ntile(16 x 256rows)][chunk(64)][32768B]
__device__ __half g_A[(size_t)MTOT * FIN];
__device__ __half g_B[(size_t)FOUT * FIN];

// quarter-ready counters (prep -> gemm), target QBLOCKS each; auto-reset by
// the last exiting GEMM CTA (g_exit), so no zeroing kernel per replay.
__device__ unsigned int g_rdy[4];
__device__ unsigned int g_exit;

#define SWZ(x) ((x) ^ (((x) >> 3) & 0x70))

__device__ __forceinline__ uint32_t h2u(__half2 h) {
    uint32_t u; memcpy(&u, &h, 4); return u;
}

__device__ __forceinline__ uint32_t smem_u32(const void* p) {
    uint32_t a;
    asm("{ .reg .u64 t; cvta.to.shared.u64 t, %1; cvt.u32.u64 %0, t; }"
        : "=r"(a) : "l"(p));
    return a;
}

// acquire-poll a global counter until it reaches tgt
__device__ __forceinline__ void wait_flag(const unsigned int* p, unsigned int tgt) {
    unsigned int v;
    while (true) {
        asm volatile("ld.acquire.gpu.global.b32 %0, [%1];"
                     : "=r"(v) : "l"(p) : "memory");
        if (v >= tgt) return;
        __nanosleep(128);
    }
}

#if HAS_TCGEN05
__device__ __forceinline__ bool elect_one() {
    uint32_t pred;
    asm volatile(
        "{\n\t.reg .pred p;\n\t"
        "elect.sync _|p, 0xFFFFFFFF;\n\t"
        "selp.b32 %0, 1, 0, p;\n\t}"
        : "=r"(pred));
    return pred != 0;
}

// SW128 K-major smem descriptor: layout=SW128(2), version=1, SBO=64, LBO=1
static constexpr unsigned long long DESC_BASE =
    (2ULL << 61) | (1ULL << 46) | (64ULL << 32) | (1ULL << 16);

__device__ __forceinline__ uint64_t make_desc(uint32_t addr) {
    return DESC_BASE | ((uint64_t)(addr >> 4) & 0x3FFF);
}

__device__ __forceinline__ void wait_parity(uint32_t mbar, int phase) {
    asm volatile(
        "{\n\t.reg .pred P;\n\t"
        "WL%=:\n\t"
        "mbarrier.try_wait.parity.acquire.cta.shared::cta.b64 P, [%0], %1, 0x989680;\n\t"
        "@P bra.uni WD%=;\n\t"
        "bra.uni WL%=;\n\t"
        "WD%=:\n\t}"
        :: "r"(mbar), "r"((uint32_t)phase) : "memory");
}

__device__ __forceinline__ void bulk_g2s(uint32_t dst, const void* src,
                                         uint32_t bytes, uint32_t mbar) {
    asm volatile(
        "cp.async.bulk.shared::cluster.global.mbarrier::complete_tx::bytes "
        "[%0], [%1], %2, [%3];"
        :: "r"(dst), "l"(src), "r"(bytes), "r"(mbar) : "memory");
}

__device__ __forceinline__ void mma_f16_ss_cg2(uint32_t d_tmem, uint64_t a_desc,
                                               uint64_t b_desc, uint32_t en) {
    asm volatile(
        "{\n\t.reg .pred p;\n\t"
        "setp.ne.u32 p, %5, 0;\n\t"
        "tcgen05.mma.cta_group::2.kind::f16 [%0], %1, %2, %3, "
        "{%4, %4, %4, %4, %4, %4, %4, %4}, p;\n\t}"
        :: "r"(d_tmem), "l"(a_desc), "l"(b_desc), "r"(IDESC_CG2),
           "r"(0u), "r"(en)
        : "memory");
}

__device__ __forceinline__ void ldtm_x32(uint32_t* r, uint32_t tmem_addr) {
    asm volatile(
        "tcgen05.ld.sync.aligned.32x32b.x32.b32 "
        "{%0, %1, %2, %3, %4, %5, %6, %7, "
        " %8, %9, %10, %11, %12, %13, %14, %15, "
        " %16, %17, %18, %19, %20, %21, %22, %23, "
        " %24, %25, %26, %27, %28, %29, %30, %31}, [%32];"
        : "=r"(r[0]),  "=r"(r[1]),  "=r"(r[2]),  "=r"(r[3]),
          "=r"(r[4]),  "=r"(r[5]),  "=r"(r[6]),  "=r"(r[7]),
          "=r"(r[8]),  "=r"(r[9]),  "=r"(r[10]), "=r"(r[11]),
          "=r"(r[12]), "=r"(r[13]), "=r"(r[14]), "=r"(r[15]),
          "=r"(r[16]), "=r"(r[17]), "=r"(r[18]), "=r"(r[19]),
          "=r"(r[20]), "=r"(r[21]), "=r"(r[22]), "=r"(r[23]),
          "=r"(r[24]), "=r"(r[25]), "=r"(r[26]), "=r"(r[27]),
          "=r"(r[28]), "=r"(r[29]), "=r"(r[30]), "=r"(r[31])
        : "r"(tmem_addr));
}
#endif  // HAS_TCGEN05

// ---------------------------------------------------------------------------
// Kernel 1: persistent fused prep, QUARTER-major item order, row-contiguous
// reads inside each quarter. item = q*3072 + i:
//   i < 1024 : cvt  — 4 rows x 1024 cols (quarter q) of inp  -> g_A
//   i >= 1024: xform — 2 rows x 1024 cols (quarter q) of W    -> g_B
// All 592 CTAs are resident in wave 1, so the PDL trigger fires immediately
// and the GEMM co-schedules; g_rdy[q] reaches 3072 when quarter q is done.
// ---------------------------------------------------------------------------
__global__ void __launch_bounds__(256, 4) prep_kernel(
    const float4* __restrict__ in, const float* __restrict__ W,
    const float* __restrict__ cw, const float* __restrict__ cb,
    const float* __restrict__ sk) {
#if defined(__CUDA_ARCH__) && __CUDA_ARCH__ >= 900
    cudaTriggerProgrammaticLaunchCompletion();
#endif
    int tid = threadIdx.x;
    for (int item = blockIdx.x; item < PREP_ITEMS; item += PREP_GRID) {
        int q = item / QBLOCKS;
        int i = item - q * QBLOCKS;
        if (i < 1024) {
            // ---- cvt: rows i*4..+4, cols q*1024..+1024 ----
            int m = i * 4 + (tid >> 6);
            int c = tid & 63;                       // 16 floats per thread
            const float4* p = in + (size_t)m * 1024 + q * 256 + c * 4;
            float4 v0 = p[0], v1 = p[1], v2 = p[2], v3 = p[3];
            uint4 u0, u1;
            u0.x = h2u(__floats2half2_rn(v0.x, v0.y));
            u0.y = h2u(__floats2half2_rn(v0.z, v0.w));
            u0.z = h2u(__floats2half2_rn(v1.x, v1.y));
            u0.w = h2u(__floats2half2_rn(v1.z, v1.w));
            u1.x = h2u(__floats2half2_rn(v2.x, v2.y));
            u1.y = h2u(__floats2half2_rn(v2.z, v2.w));
            u1.z = h2u(__floats2half2_rn(v3.x, v3.y));
            u1.w = h2u(__floats2half2_rn(v3.z, v3.w));
            int kv = q * 128 + c * 2;               // even, so kv & kv+1 same blk
            char* base = reinterpret_cast<char*>(g_A) +
                         (size_t)((m >> 7) * 64 + (kv >> 3)) * A_BYTES;
            uint32_t rb = (uint32_t)(m & 127) * 128;
            *reinterpret_cast<uint4*>(base + SWZ(rb + (kv & 7) * 16)) = u0;
            *reinterpret_cast<uint4*>(base + SWZ(rb + ((kv + 1) & 7) * 16)) = u1;
        } else {
            // ---- xform: rows (i-1024)*2..+2, cols q*1024..+1024 ----
            int j = i - 1024;
            int row = j * 2 + (tid >> 7);
            int seg = tid & 127;                    // 8 cols per thread
            int cc = q * 1024 + seg * 8;
            int h = row >> 10, r = row & 1023;

            float kk[9];
#pragma unroll
            for (int t = 0; t < 9; ++t) kk[t] = cw[h * 9 + t];
            float bias = cb[h];
            float gate = 1.0f / (1.0f + expf(-sk[h]));

            float acc[8], cen[8];
#pragma unroll
            for (int t = 0; t < 8; ++t) acc[t] = bias;

            const float* wb = W + (size_t)(h << 10) * FIN;
#pragma unroll
            for (int dr = -1; dr <= 1; ++dr) {
                int rr = r + dr;
                if (rr < 0 || rr > 1023) continue;
                const float* rp = wb + (size_t)rr * FIN;
                float x[10];
                x[0] = (cc > 0) ? rp[cc - 1] : 0.f;
                float4 a = *reinterpret_cast<const float4*>(rp + cc);
                float4 b = *reinterpret_cast<const float4*>(rp + cc + 4);
                x[1] = a.x; x[2] = a.y; x[3] = a.z; x[4] = a.w;
                x[5] = b.x; x[6] = b.y; x[7] = b.z; x[8] = b.w;
                x[9] = (cc + 8 < FIN) ? rp[cc + 8] : 0.f;
                if (dr == 0) {
#pragma unroll
                    for (int t = 0; t < 8; ++t) cen[t] = x[t + 1];
                }
                int kr = (dr + 1) * 3;
#pragma unroll
                for (int t = 0; t < 8; ++t)
                    acc[t] += kk[kr] * x[t] + kk[kr + 1] * x[t + 1] +
                              kk[kr + 2] * x[t + 2];
            }

            uint4 u;
            u.x = h2u(__floats2half2_rn(acc[0] + gate * cen[0], acc[1] + gate * cen[1]));
            u.y = h2u(__floats2half2_rn(acc[2] + gate * cen[2], acc[3] + gate * cen[3]));
            u.z = h2u(__floats2half2_rn(acc[4] + gate * cen[4], acc[5] + gate * cen[5]));
            u.w = h2u(__floats2half2_rn(acc[6] + gate * cen[6], acc[7] + gate * cen[7]));
            int kv = q * 128 + seg;
            char* base = reinterpret_cast<char*>(g_B) +
                         (size_t)((row >> 8) * 64 + (kv >> 3)) * 32768;
            *reinterpret_cast<uint4*>(base +
                SWZ((uint32_t)(row & 255) * 128 + (kv & 7) * 16)) = u;
        }
        __threadfence();
        __syncthreads();
        if (tid == 0) atomicAdd(&g_rdy[q], 1u);
    }
}

// ---------------------------------------------------------------------------
// Kernel 2: cg2 tcgen05 GEMM (R10 structure). CTA-pair computes 256x512;
// producers gate each chunk on its quarter counter so the kernel can run
// concurrently with prep under PDL. Last exiting CTA resets the counters.
// ---------------------------------------------------------------------------
__global__ void __launch_bounds__(256, 1) __cluster_dims__(2, 1, 1)
gemm_kernel(float* __restrict__ out) {
    extern __shared__ char smem[];
    int tid = threadIdx.x;
    int pn = blockIdx.x >> 1;        // 8 n-pairs (512 cols each)
    int rank = blockIdx.x & 1;       // cg2 pair rank
    int pm = blockIdx.y;             // 16 m-pairs (256 rows each)

#if HAS_TCGEN05
    uint32_t sb = smem_u32(smem);
    int wid = tid >> 5, lid = tid & 31;

    if (tid == 0) {
#pragma unroll
        for (int s = 0; s < NSTAGE; ++s) {
            // leader full: expect_tx arrive + follower relay arrive = 2
            asm volatile("mbarrier.init.shared.b64 [%0], %1;"
                         :: "r"(sb + SM_BAR + s * 16),
                            "r"(rank == 0 ? 2u : 1u) : "memory");
            asm volatile("mbarrier.init.shared.b64 [%0], 1;"
                         :: "r"(sb + SM_BAR + s * 16 + 8) : "memory");   // empty
        }
        asm volatile("mbarrier.init.shared.b64 [%0], 1;"
                     :: "r"(sb + SM_DONE) : "memory");
    }
    if (wid == 0) {
        asm volatile("tcgen05.alloc.cta_group::2.sync.aligned.shared::cta.b32 [%0], 512;"
                     :: "r"(sb) : "memory");
        asm volatile("tcgen05.relinquish_alloc_permit.cta_group::2.sync.aligned;");
    }
    __syncthreads();
    asm volatile("barrier.cluster.arrive.aligned;" ::: "memory");
    asm volatile("barrier.cluster.wait.aligned;" ::: "memory");

    uint32_t tmem;
    asm volatile("ld.shared.b32 %0, [%1];" : "=r"(tmem) : "r"(sb));

    if (wid == 0 && elect_one()) {
        // ---- producer: stage own A-half + own two B-splits ----
        const char* gAp = reinterpret_cast<const char*>(g_A) +
                          (size_t)(pm * 2 + rank) * 64 * A_BYTES;
        const char* gB0 = reinterpret_cast<const char*>(g_B) +
                          (size_t)(pn * 2) * 64 * 32768 + (size_t)rank * 16384;
        const char* gB1 = reinterpret_cast<const char*>(g_B) +
                          (size_t)(pn * 2 + 1) * 64 * 32768 + (size_t)rank * 16384;
        int eph[NSTAGE] = {0, 0, 0, 0};
        for (int i = 0; i < KCHUNKS; ++i) {
            int s = i & (NSTAGE - 1);
            uint32_t full = sb + SM_BAR + s * 16;
            if (i >= NSTAGE) { wait_parity(full + 8, eph[s]); eph[s] ^= 1; }
            wait_flag(&g_rdy[i >> 4], (unsigned)QBLOCKS);   // quarter produced?
            asm volatile("mbarrier.arrive.expect_tx.shared.b64 _, [%0], %1;"
                         :: "r"(full), "r"((uint32_t)TX_BYTES) : "memory");
            uint32_t dst = sb + SM_TILE0 + s * STAGE_BYTES;
            bulk_g2s(dst,         gAp + (size_t)i * A_BYTES, A_BYTES, full);
            bulk_g2s(dst + 16384, gB0 + (size_t)i * 32768, BH_BYTES, full);
            bulk_g2s(dst + 32768, gB1 + (size_t)i * 32768, BH_BYTES, full);
        }
    } else if (wid == 1 && elect_one()) {
        if (rank == 0) {
            // ---- consumer (leader): 8 cg2 MMAs per chunk ----
            int fph[NSTAGE] = {0, 0, 0, 0};
            for (int i = 0; i < KCHUNKS; ++i) {
                int s = i & (NSTAGE - 1);
                uint32_t full = sb + SM_BAR + s * 16;
                wait_parity(full, fph[s]); fph[s] ^= 1;
                uint32_t sA = sb + SM_TILE0 + s * STAGE_BYTES;
                uint64_t ad  = make_desc(sA);
                uint64_t bd0 = make_desc(sA + 16384);
                uint64_t bd1 = make_desc(sA + 32768);
#pragma unroll
                for (int ks = 0; ks < 4; ++ks) {   // K=16 steps; +32B per step
                    uint32_t en = (uint32_t)(i | ks);
                    mma_f16_ss_cg2(tmem,       ad + ks * 2, bd0 + ks * 2, en);
                    mma_f16_ss_cg2(tmem + 256, ad + ks * 2, bd1 + ks * 2, en);
                }
                if (i < KCHUNKS - 1) {
                    asm volatile(
                        "tcgen05.commit.cta_group::2.mbarrier::arrive::one."
                        "shared::cluster.multicast::cluster.b64 [%0], %1;"
                        :: "r"(full + 8), "h"((uint16_t)0x3) : "memory");
                } else {
                    asm volatile(
                        "tcgen05.commit.cta_group::2.mbarrier::arrive::one."
                        "shared::cluster.multicast::cluster.b64 [%0], %1;"
                        :: "r"(sb + SM_DONE), "h"((uint16_t)0x3) : "memory");
                }
            }
        } else {
            // ---- relay (follower): own data ready -> arrive leader's full ----
            int fph[NSTAGE] = {0, 0, 0, 0};
            for (int i = 0; i < KCHUNKS; ++i) {
                int s = i & (NSTAGE - 1);
                uint32_t full = sb + SM_BAR + s * 16;
                wait_parity(full, fph[s]); fph[s] ^= 1;
                asm volatile("mbarrier.arrive.shared::cluster.b64 _, [%0];"
                             :: "r"(full & PEER_MASK) : "memory");
            }
        }
    }

    // all warps (both CTAs): wait for full accumulation
    wait_parity(sb + SM_DONE, 0);
    asm volatile("tcgen05.fence::after_thread_sync;" ::: "memory");
    __syncthreads();

    // Epilogue: rows pm*256 + rank*128 .. +128, cols pn*512 .. +512.
    int sp = wid & 3, halfc = wid >> 2;
    float* scr = reinterpret_cast<float*>(smem + 1024 + wid * 4224);  // 32x33 f32
    int rowb = pm * 256 + rank * 128 + sp * 32;
    int col0 = pn * 512 + halfc * 256;
#pragma unroll 1
    for (int cb = 0; cb < 8; ++cb) {
        uint32_t regs[32];
        uint32_t ta = tmem + (uint32_t)(halfc * 256 + cb * 32) + ((uint32_t)sp << 21);
        ldtm_x32(regs, ta);
        asm volatile("tcgen05.wait::ld.sync.aligned;" ::: "memory");
#pragma unroll
        for (int j = 0; j < 32; ++j) scr[lid * 33 + j] = __uint_as_float(regs[j]);
        __syncwarp();
#pragma unroll 4
        for (int r2 = 0; r2 < 32; ++r2)
            out[(size_t)(rowb + r2) * FOUT + col0 + cb * 32 + lid] = scr[r2 * 33 + lid];
        __syncwarp();
    }
    asm volatile("tcgen05.fence::before_thread_sync;" ::: "memory");
    __syncthreads();
    if (wid == 0) {
        asm volatile("tcgen05.dealloc.cta_group::2.sync.aligned.b32 %0, 512;" :: "r"(tmem));
    }
    asm volatile("barrier.cluster.arrive.aligned;" ::: "memory");
    asm volatile("barrier.cluster.wait.aligned;" ::: "memory");

    // last exiting CTA resets the quarter counters for the next graph replay
    if (tid == 0) {
        __threadfence();
        unsigned int old = atomicAdd(&g_exit, 1u);
        if (old == GEMM_CTAS - 1u) {
            g_rdy[0] = 0; g_rdy[1] = 0; g_rdy[2] = 0; g_rdy[3] = 0;
            __threadfence();
            atomicExch(&g_exit, 0u);
        }
    }

#else  // ---------- FFMA fallback (plain sm_103 pass; correctness safety net) ----
    __half* tA = reinterpret_cast<__half*>(smem + SM_TILE0);            // 128x64
    __half* tB = reinterpret_cast<__half*>(smem + SM_TILE0 + 16384);    // 256x64
    int tm = tid >> 4, tn = tid & 15;
    int mt = pm * 2 + rank;
    int m0f = mt << 7;

    const uint4* gA4 = reinterpret_cast<const uint4*>(g_A);
    const uint4* gB4 = reinterpret_cast<const uint4*>(g_B);

    for (int qn = 0; qn < 2; ++qn) {
        int nt = pn * 2 + qn;
        int n0f = nt << 8;
        float acc[8][16];
#pragma unroll
        for (int r = 0; r < 8; ++r)
#pragma unroll
            for (int c = 0; c < 16; ++c) acc[r][c] = 0.f;

        for (int i = 0; i < KCHUNKS; ++i) {
            if (tid == 0) wait_flag(&g_rdy[i >> 4], (unsigned)QBLOCKS);
            __syncthreads();
            uint32_t blkA = (uint32_t)mt * 64 + i;
            uint32_t blkB = (uint32_t)nt * 64 + i;
#pragma unroll
            for (int it = 0; it < 4; ++it) {
                int t = tid + it * 256;
                int r = t >> 3, v = t & 7;
                reinterpret_cast<uint4*>(tA)[r * 8 + v] =
                    gA4[(size_t)blkA * 1024 + (SWZ((uint32_t)(r * 128 + v * 16)) >> 4)];
            }
#pragma unroll
            for (int it = 0; it < 8; ++it) {
                int t = tid + it * 256;
                int r = t >> 3, v = t & 7;
                reinterpret_cast<uint4*>(tB)[r * 8 + v] =
                    gB4[(size_t)blkB * 2048 + (SWZ((uint32_t)(r * 128 + v * 16)) >> 4)];
            }
            __syncthreads();

            for (int k = 0; k < 64; ++k) {
                float av[8], bv[16];
#pragma unroll
                for (int r = 0; r < 8; ++r) av[r] = __half2float(tA[(tm * 8 + r) * 64 + k]);
#pragma unroll
                for (int c = 0; c < 16; ++c) bv[c] = __half2float(tB[(tn * 16 + c) * 64 + k]);
#pragma unroll
                for (int r = 0; r < 8; ++r)
#pragma unroll
                    for (int c = 0; c < 16; ++c) acc[r][c] += av[r] * bv[c];
            }
            __syncthreads();
        }
#pragma unroll
        for (int r = 0; r < 8; ++r)
#pragma unroll
            for (int c = 0; c < 16; ++c)
                out[(size_t)(m0f + tm * 8 + r) * FOUT + n0f + tn * 16 + c] = acc[r][c];
        __syncthreads();
    }

    if (tid == 0) {
        __threadfence();
        unsigned int old = atomicAdd(&g_exit, 1u);
        if (old == GEMM_CTAS - 1u) {
            g_rdy[0] = 0; g_rdy[1] = 0; g_rdy[2] = 0; g_rdy[3] = 0;
            __threadfence();
            atomicExch(&g_exit, 0u);
        }
    }
#endif
}

// ---------------------------------------------------------------------------
extern "C" void kernel_launch(void* const* d_in, const int* in_sizes, int n_in,
                              void* d_out, int out_size) {
    const float* inp = (const float*)d_in[0];  // [2, 2048, 4096]
    const float* W   = (const float*)d_in[1];  // [4096, 4096]
    const float* cw  = (const float*)d_in[2];  // [4, 1, 3, 3]
    const float* cb  = (const float*)d_in[3];  // [4]
    const float* sk  = (const float*)d_in[4];  // [4, 1, 1]
    float* out = (float*)d_out;                // [2, 2048, 4096]

    cudaFuncSetAttribute(gemm_kernel,
                         cudaFuncAttributeMaxDynamicSharedMemorySize, SMEM_BYTES);

    prep_kernel<<<PREP_GRID, 256>>>((const float4*)inp, W, cw, cb, sk);

    // GEMM with programmatic dependent launch: co-schedules with prep;
    // quarter flags gate the actual data consumption.
    cudaLaunchConfig_t cfg = {};
    cfg.gridDim = dim3(16, 16, 1);
    cfg.blockDim = dim3(256, 1, 1);
    cfg.dynamicSmemBytes = SMEM_BYTES;
    cfg.stream = 0;
    cudaLaunchAttribute at[1];
    at[0].id = cudaLaunchAttributeProgrammaticStreamSerialization;
    at[0].val.programmaticStreamSerializationAllowed = 1;
    cfg.attrs = at;
    cfg.numAttrs = 1;
    cudaError_t e = cudaLaunchKernelEx(&cfg, gemm_kernel, out);
    if (e != cudaSuccess) {
        // PDL unavailable: plain serialized launch (flags already satisfied).
        gemm_kernel<<<dim3(16, 16), 256, SMEM_BYTES>>>(out);
    }
}

// round 13
// speedup vs baseline: 1.1848x; 1.0522x over previous
#include <cuda_runtime.h>
#include <cuda_fp16.h>
#include <cstdint>
#include <cstring>

// Problem dims
#define FIN   4096
#define FOUT  4096
#define MTOT  4096   // 2 * 2048

#define KCHUNKS 64          // K chunks of 64
#define NSTAGE  4
#define A_BYTES      16384  // 128 rows x 128B (this CTA's M-half)
#define BH_BYTES     16384  // one B half: 128 rows x 128B
#define STAGE_BYTES  49152  // A + B0half + B1half
#define TX_BYTES     49152  // per-CTA TMA bytes per stage

// Persistent schedule: 128 tiles (256M x 512N) over 74 cg2 pairs.
#define NPAIRS   74
#define NTILES   128
#define TWOTILE  (NTILES - NPAIRS)   // 54 pairs run 2 tiles

// SMEM layout (dynamic):
//   [0..4)      TMEM base ptr
//   [8..72)     full[s]=8+16s, empty[s]=16+16s  (s=0..3)
//   [72..80)    done mbarrier   (per-tile, parity 0 then 1)
//   [80..88)    epifree mbarrier (count 2, single use)
//   [1024 + s*49152)  stage s: A(16K) | B0half(16K) | B1half(16K)
//   [197632..214528)  epilogue scratch: 4 warps x 4224B
#define SM_BAR     8
#define SM_DONE    72
#define SM_EPIFREE 80
#define SM_TILE0   1024
#define SM_SCRATCH (1024 + NSTAGE * STAGE_BYTES)          // 197632
#define SMEM_BYTES (SM_SCRATCH + 4 * 4224)                // 214528, occ 1

// idesc kind::f16 cg2: dtype=F32(1<<4), a/b=F16(0), N=256 -> 32<<17,
// M=256 -> 16<<24
#define IDESC_CG2 0x10400010u
#define PEER_MASK 0xFEFFFFFFu

#if defined(__CUDA_ARCH__) && \
    (defined(__CUDA_ARCH_FEAT_SM103_ALL) || defined(__CUDA_ARCH_FEAT_SM100_ALL) || \
     defined(__CUDA_ARCH_FEAT_SM101_ALL))
#define HAS_TCGEN05 1
#else
#define HAS_TCGEN05 0
#endif

// fp16 staging in chunk-blocked, pre-SW128-swizzled layout:
// g_A: [mtile(32 x 128rows)][chunk(64)][16384B]
// g_B: [ntile(16 x 256rows)][chunk(64)][32768B]
__device__ __half g_A[(size_t)MTOT * FIN];
__device__ __half g_B[(size_t)FOUT * FIN];

#define SWZ(x) ((x) ^ (((x) >> 3) & 0x70))

__device__ __forceinline__ uint32_t h2u(__half2 h) {
    uint32_t u; memcpy(&u, &h, 4); return u;
}

__device__ __forceinline__ uint32_t smem_u32(const void* p) {
    uint32_t a;
    asm("{ .reg .u64 t; cvta.to.shared.u64 t, %1; cvt.u32.u64 %0, t; }"
        : "=r"(a) : "l"(p));
    return a;
}

#if HAS_TCGEN05
__device__ __forceinline__ bool elect_one() {
    uint32_t pred;
    asm volatile(
        "{\n\t.reg .pred p;\n\t"
        "elect.sync _|p, 0xFFFFFFFF;\n\t"
        "selp.b32 %0, 1, 0, p;\n\t}"
        : "=r"(pred));
    return pred != 0;
}

// SW128 K-major smem descriptor: layout=SW128(2), version=1, SBO=64, LBO=1
static constexpr unsigned long long DESC_BASE =
    (2ULL << 61) | (1ULL << 46) | (64ULL << 32) | (1ULL << 16);

__device__ __forceinline__ uint64_t make_desc(uint32_t addr) {
    return DESC_BASE | ((uint64_t)(addr >> 4) & 0x3FFF);
}

__device__ __forceinline__ void wait_parity(uint32_t mbar, int phase) {
    asm volatile(
        "{\n\t.reg .pred P;\n\t"
        "WL%=:\n\t"
        "mbarrier.try_wait.parity.acquire.cta.shared::cta.b64 P, [%0], %1, 0x989680;\n\t"
        "@P bra.uni WD%=;\n\t"
        "bra.uni WL%=;\n\t"
        "WD%=:\n\t}"
        :: "r"(mbar), "r"((uint32_t)phase) : "memory");
}

__device__ __forceinline__ void bulk_g2s(uint32_t dst, const void* src,
                                         uint32_t bytes, uint32_t mbar) {
    asm volatile(
        "cp.async.bulk.shared::cluster.global.mbarrier::complete_tx::bytes "
        "[%0], [%1], %2, [%3];"
        :: "r"(dst), "l"(src), "r"(bytes), "r"(mbar) : "memory");
}

__device__ __forceinline__ void mma_f16_ss_cg2(uint32_t d_tmem, uint64_t a_desc,
                                               uint64_t b_desc, uint32_t en) {
    asm volatile(
        "{\n\t.reg .pred p;\n\t"
        "setp.ne.u32 p, %5, 0;\n\t"
        "tcgen05.mma.cta_group::2.kind::f16 [%0], %1, %2, %3, "
        "{%4, %4, %4, %4, %4, %4, %4, %4}, p;\n\t}"
        :: "r"(d_tmem), "l"(a_desc), "l"(b_desc), "r"(IDESC_CG2),
           "r"(0u), "r"(en)
        : "memory");
}

__device__ __forceinline__ void ldtm_x32(uint32_t* r, uint32_t tmem_addr) {
    asm volatile(
        "tcgen05.ld.sync.aligned.32x32b.x32.b32 "
        "{%0, %1, %2, %3, %4, %5, %6, %7, "
        " %8, %9, %10, %11, %12, %13, %14, %15, "
        " %16, %17, %18, %19, %20, %21, %22, %23, "
        " %24, %25, %26, %27, %28, %29, %30, %31}, [%32];"
        : "=r"(r[0]),  "=r"(r[1]),  "=r"(r[2]),  "=r"(r[3]),
          "=r"(r[4]),  "=r"(r[5]),  "=r"(r[6]),  "=r"(r[7]),
          "=r"(r[8]),  "=r"(r[9]),  "=r"(r[10]), "=r"(r[11]),
          "=r"(r[12]), "=r"(r[13]), "=r"(r[14]), "=r"(r[15]),
          "=r"(r[16]), "=r"(r[17]), "=r"(r[18]), "=r"(r[19]),
          "=r"(r[20]), "=r"(r[21]), "=r"(r[22]), "=r"(r[23]),
          "=r"(r[24]), "=r"(r[25]), "=r"(r[26]), "=r"(r[27]),
          "=r"(r[28]), "=r"(r[29]), "=r"(r[30]), "=r"(r[31])
        : "r"(tmem_addr));
}
#endif  // HAS_TCGEN05

// ---------------------------------------------------------------------------
// Kernel 1: fp32 -> fp16 convert of inp -> chunk-blocked swizzled g_A.
// (R10 version — measured 14.8us)
// ---------------------------------------------------------------------------
__global__ void __launch_bounds__(256) cvt_inp_kernel(const float4* __restrict__ in) {
    int i = blockIdx.x * 256 + threadIdx.x;     // 0 .. 2M-1
    int m = i >> 9, kv = i & 511;
    float4 v0 = in[(size_t)m * 1024 + kv * 2];
    float4 v1 = in[(size_t)m * 1024 + kv * 2 + 1];
    uint4 u;
    u.x = h2u(__floats2half2_rn(v0.x, v0.y));
    u.y = h2u(__floats2half2_rn(v0.z, v0.w));
    u.z = h2u(__floats2half2_rn(v1.x, v1.y));
    u.w = h2u(__floats2half2_rn(v1.z, v1.w));
    uint32_t blk = (uint32_t)(m >> 7) * 64 + (kv >> 3);
    uint32_t off = SWZ((uint32_t)(m & 127) * 128 + (kv & 7) * 16);
    *reinterpret_cast<uint4*>(reinterpret_cast<char*>(g_A) +
                              (size_t)blk * A_BYTES + off) = u;
}

// ---------------------------------------------------------------------------
// Kernel 2: weight transform -> chunk-blocked swizzled g_B. (R10 version)
// ---------------------------------------------------------------------------
__global__ void __launch_bounds__(512) xform_w_kernel(
    const float* __restrict__ W, const float* __restrict__ cw,
    const float* __restrict__ cb, const float* __restrict__ sk) {
    int row = blockIdx.x;          // fout index 0..4095
    int tid = threadIdx.x;         // 0..511
    int c0 = tid * 8;
    int h = row >> 10, r = row & 1023;

    float kk[9];
#pragma unroll
    for (int j = 0; j < 9; ++j) kk[j] = cw[h * 9 + j];
    float bias = cb[h];
    float gate = 1.0f / (1.0f + expf(-sk[h]));

    float acc[8], cen[8];
#pragma unroll
    for (int j = 0; j < 8; ++j) acc[j] = bias;

    const float* base = W + (size_t)(h << 10) * FIN;
#pragma unroll
    for (int dr = -1; dr <= 1; ++dr) {
        int rr = r + dr;
        if (rr < 0 || rr > 1023) continue;
        const float* rp = base + (size_t)rr * FIN;
        float x[10];
        x[0] = (c0 > 0) ? rp[c0 - 1] : 0.f;
        float4 a = *reinterpret_cast<const float4*>(rp + c0);
        float4 b = *reinterpret_cast<const float4*>(rp + c0 + 4);
        x[1] = a.x; x[2] = a.y; x[3] = a.z; x[4] = a.w;
        x[5] = b.x; x[6] = b.y; x[7] = b.z; x[8] = b.w;
        x[9] = (c0 + 8 < FIN) ? rp[c0 + 8] : 0.f;
        if (dr == 0) {
#pragma unroll
            for (int j = 0; j < 8; ++j) cen[j] = x[j + 1];
        }
        int kr = (dr + 1) * 3;
#pragma unroll
        for (int j = 0; j < 8; ++j)
            acc[j] += kk[kr] * x[j] + kk[kr + 1] * x[j + 1] + kk[kr + 2] * x[j + 2];
    }

    uint4 u;
    u.x = h2u(__floats2half2_rn(acc[0] + gate * cen[0], acc[1] + gate * cen[1]));
    u.y = h2u(__floats2half2_rn(acc[2] + gate * cen[2], acc[3] + gate * cen[3]));
    u.z = h2u(__floats2half2_rn(acc[4] + gate * cen[4], acc[5] + gate * cen[5]));
    u.w = h2u(__floats2half2_rn(acc[6] + gate * cen[6], acc[7] + gate * cen[7]));
    uint32_t blk = (uint32_t)(row >> 8) * 64 + (tid >> 3);
    uint32_t off = SWZ((uint32_t)(row & 255) * 128 + (tid & 7) * 16);
    *reinterpret_cast<uint4*>(reinterpret_cast<char*>(g_B) +
                              (size_t)blk * 32768 + off) = u;
}

// ---------------------------------------------------------------------------
// Kernel 3: PERSISTENT cg2 tcgen05 GEMM. 74 pairs, each runs 1-2 tiles of
// 256(M) x 512(N). One TMEM alloc + one pipeline fill per pair; TMA stream
// continues across the tile boundary while warps 4-7 drain tile 1's TMEM
// (done barrier) and release it (epifree barrier) for tile 2's MMAs.
// ---------------------------------------------------------------------------
__global__ void __launch_bounds__(256, 1) __cluster_dims__(2, 1, 1)
gemm_kernel(float* __restrict__ out) {
    extern __shared__ char smem[];
    int tid = threadIdx.x;
    int p = blockIdx.x >> 1;         // pair id 0..73
    int rank = blockIdx.x & 1;       // cg2 pair rank
    int ntiles = (p < TWOTILE) ? 2 : 1;

#if HAS_TCGEN05
    uint32_t sb = smem_u32(smem);
    int wid = tid >> 5, lid = tid & 31;

    if (tid == 0) {
#pragma unroll
        for (int s = 0; s < NSTAGE; ++s) {
            // leader full: expect_tx arrive + follower relay arrive = 2
            asm volatile("mbarrier.init.shared.b64 [%0], %1;"
                         :: "r"(sb + SM_BAR + s * 16),
                            "r"(rank == 0 ? 2u : 1u) : "memory");
            asm volatile("mbarrier.init.shared.b64 [%0], 1;"
                         :: "r"(sb + SM_BAR + s * 16 + 8) : "memory");   // empty
        }
        asm volatile("mbarrier.init.shared.b64 [%0], 1;"
                     :: "r"(sb + SM_DONE) : "memory");
        asm volatile("mbarrier.init.shared.b64 [%0], 2;"
                     :: "r"(sb + SM_EPIFREE) : "memory");
    }
    if (wid == 0) {
        asm volatile("tcgen05.alloc.cta_group::2.sync.aligned.shared::cta.b32 [%0], 512;"
                     :: "r"(sb) : "memory");
        asm volatile("tcgen05.relinquish_alloc_permit.cta_group::2.sync.aligned;");
    }
    __syncthreads();
    asm volatile("barrier.cluster.arrive.aligned;" ::: "memory");
    asm volatile("barrier.cluster.wait.aligned;" ::: "memory");

    uint32_t tmem;
    asm volatile("ld.shared.b32 %0, [%1];" : "=r"(tmem) : "r"(sb));

    int total = ntiles * KCHUNKS;

    if (wid == 0 && elect_one()) {
        // ---- producer: flat chunk stream across tiles ----
        int eph[NSTAGE] = {0, 0, 0, 0};
        for (int c = 0; c < total; ++c) {
            int t = (c >= KCHUNKS) ? 1 : 0;
            int k = c & (KCHUNKS - 1);
            int s = c & (NSTAGE - 1);
            int tl = (t == 0) ? p : (p + NPAIRS);
            int pm = tl & 15, pn = tl >> 4;
            uint32_t full = sb + SM_BAR + s * 16;
            if (c >= NSTAGE) { wait_parity(full + 8, eph[s]); eph[s] ^= 1; }
            const char* gAp = reinterpret_cast<const char*>(g_A) +
                              (size_t)(pm * 2 + rank) * 64 * A_BYTES;
            const char* gB0 = reinterpret_cast<const char*>(g_B) +
                              (size_t)(pn * 2) * 64 * 32768 + (size_t)rank * 16384;
            const char* gB1 = reinterpret_cast<const char*>(g_B) +
                              (size_t)(pn * 2 + 1) * 64 * 32768 + (size_t)rank * 16384;
            asm volatile("mbarrier.arrive.expect_tx.shared.b64 _, [%0], %1;"
                         :: "r"(full), "r"((uint32_t)TX_BYTES) : "memory");
            uint32_t dst = sb + SM_TILE0 + s * STAGE_BYTES;
            bulk_g2s(dst,         gAp + (size_t)k * A_BYTES, A_BYTES, full);
            bulk_g2s(dst + 16384, gB0 + (size_t)k * 32768, BH_BYTES, full);
            bulk_g2s(dst + 32768, gB1 + (size_t)k * 32768, BH_BYTES, full);
        }
    } else if (wid == 1 && elect_one()) {
        if (rank == 0) {
            // ---- consumer (leader): 8 cg2 MMAs per chunk ----
            int fph[NSTAGE] = {0, 0, 0, 0};
            for (int c = 0; c < total; ++c) {
                int k = c & (KCHUNKS - 1);
                int s = c & (NSTAGE - 1);
                uint32_t full = sb + SM_BAR + s * 16;
                wait_parity(full, fph[s]); fph[s] ^= 1;
                if (c == KCHUNKS) {
                    // tile 2 reuses TMEM: wait for both CTAs' epilogues
                    wait_parity(sb + SM_EPIFREE, 0);
                    asm volatile("tcgen05.fence::after_thread_sync;" ::: "memory");
                }
                uint32_t sA = sb + SM_TILE0 + s * STAGE_BYTES;
                uint64_t ad  = make_desc(sA);
                uint64_t bd0 = make_desc(sA + 16384);
                uint64_t bd1 = make_desc(sA + 32768);
#pragma unroll
                for (int ks = 0; ks < 4; ++ks) {   // K=16 steps; +32B per step
                    uint32_t en = (uint32_t)(k | ks);   // k tile-local -> reset per tile
                    mma_f16_ss_cg2(tmem,       ad + ks * 2, bd0 + ks * 2, en);
                    mma_f16_ss_cg2(tmem + 256, ad + ks * 2, bd1 + ks * 2, en);
                }
                // free the stage in both CTAs
                asm volatile(
                    "tcgen05.commit.cta_group::2.mbarrier::arrive::one."
                    "shared::cluster.multicast::cluster.b64 [%0], %1;"
                    :: "r"(full + 8), "h"((uint16_t)0x3) : "memory");
                if (k == KCHUNKS - 1) {
                    // tile finished -> arm done in both CTAs
                    asm volatile(
                        "tcgen05.commit.cta_group::2.mbarrier::arrive::one."
                        "shared::cluster.multicast::cluster.b64 [%0], %1;"
                        :: "r"(sb + SM_DONE), "h"((uint16_t)0x3) : "memory");
                }
            }
        } else {
            // ---- relay (follower): own data ready -> arrive leader's full ----
            int fph[NSTAGE] = {0, 0, 0, 0};
            for (int c = 0; c < total; ++c) {
                int s = c & (NSTAGE - 1);
                uint32_t full = sb + SM_BAR + s * 16;
                wait_parity(full, fph[s]); fph[s] ^= 1;
                asm volatile("mbarrier.arrive.shared::cluster.b64 _, [%0];"
                             :: "r"(full & PEER_MASK) : "memory");
            }
        }
    }

    // ---- epilogue warps 4..7: one per TMEM subpartition ----
    if (wid >= 4) {
        int sp = wid - 4;
        float* scr = reinterpret_cast<float*>(smem + SM_SCRATCH + sp * 4224);
        for (int t = 0; t < ntiles; ++t) {
            wait_parity(sb + SM_DONE, t);
            asm volatile("tcgen05.fence::after_thread_sync;" ::: "memory");
            int tl = (t == 0) ? p : (p + NPAIRS);
            int pm = tl & 15, pn = tl >> 4;
            int rowb = pm * 256 + rank * 128 + sp * 32;
            int colb = pn * 512;
#pragma unroll 1
            for (int cb = 0; cb < 16; ++cb) {
                uint32_t regs[32];
                ldtm_x32(regs, tmem + (uint32_t)(cb * 32) + ((uint32_t)sp << 21));
                asm volatile("tcgen05.wait::ld.sync.aligned;" ::: "memory");
#pragma unroll
                for (int j = 0; j < 32; ++j) scr[lid * 33 + j] = __uint_as_float(regs[j]);
                __syncwarp();
#pragma unroll 4
                for (int r2 = 0; r2 < 32; ++r2)
                    out[(size_t)(rowb + r2) * FOUT + colb + cb * 32 + lid] =
                        scr[r2 * 33 + lid];
                __syncwarp();
            }
            if (t == 0 && ntiles == 2) {
                asm volatile("tcgen05.fence::before_thread_sync;" ::: "memory");
                // all 4 epilogue warps of this CTA done with tile 1's TMEM
                asm volatile("bar.sync 2, 128;" ::: "memory");
                if (sp == 0 && elect_one()) {
                    asm volatile("mbarrier.arrive.shared::cluster.b64 _, [%0];"
                                 :: "r"((sb + SM_EPIFREE) & PEER_MASK) : "memory");
                }
            }
        }
        asm volatile("tcgen05.fence::before_thread_sync;" ::: "memory");
    }

    __syncthreads();
    if (wid == 0) {
        asm volatile("tcgen05.dealloc.cta_group::2.sync.aligned.b32 %0, 512;" :: "r"(tmem));
    }
    asm volatile("barrier.cluster.arrive.aligned;" ::: "memory");
    asm volatile("barrier.cluster.wait.aligned;" ::: "memory");

#else  // ---------- FFMA fallback (plain sm_103 pass; correctness safety net) ----
    __half* tA = reinterpret_cast<__half*>(smem + SM_TILE0);            // 128x64
    __half* tB = reinterpret_cast<__half*>(smem + SM_TILE0 + 16384);    // 256x64
    int tm = tid >> 4, tn = tid & 15;

    const uint4* gA4 = reinterpret_cast<const uint4*>(g_A);
    const uint4* gB4 = reinterpret_cast<const uint4*>(g_B);

    for (int t = 0; t < ntiles; ++t) {
        int tl = (t == 0) ? p : (p + NPAIRS);
        int pm = tl & 15, pn = tl >> 4;
        int mt = pm * 2 + rank;
        int m0f = mt << 7;
        for (int qn = 0; qn < 2; ++qn) {
            int nt = pn * 2 + qn;
            int n0f = nt << 8;
            float acc[8][16];
#pragma unroll
            for (int r = 0; r < 8; ++r)
#pragma unroll
                for (int c = 0; c < 16; ++c) acc[r][c] = 0.f;

            for (int i = 0; i < KCHUNKS; ++i) {
                __syncthreads();
                uint32_t blkA = (uint32_t)mt * 64 + i;
                uint32_t blkB = (uint32_t)nt * 64 + i;
#pragma unroll
                for (int it = 0; it < 4; ++it) {
                    int tt = tid + it * 256;
                    int r = tt >> 3, v = tt & 7;
                    reinterpret_cast<uint4*>(tA)[r * 8 + v] =
                        gA4[(size_t)blkA * 1024 + (SWZ((uint32_t)(r * 128 + v * 16)) >> 4)];
                }
#pragma unroll
                for (int it = 0; it < 8; ++it) {
                    int tt = tid + it * 256;
                    int r = tt >> 3, v = tt & 7;
                    reinterpret_cast<uint4*>(tB)[r * 8 + v] =
                        gB4[(size_t)blkB * 2048 + (SWZ((uint32_t)(r * 128 + v * 16)) >> 4)];
                }
                __syncthreads();

                for (int k = 0; k < 64; ++k) {
                    float av[8], bv[16];
#pragma unroll
                    for (int r = 0; r < 8; ++r)
                        av[r] = __half2float(tA[(tm * 8 + r) * 64 + k]);
#pragma unroll
                    for (int c = 0; c < 16; ++c)
                        bv[c] = __half2float(tB[(tn * 16 + c) * 64 + k]);
#pragma unroll
                    for (int r = 0; r < 8; ++r)
#pragma unroll
                        for (int c = 0; c < 16; ++c) acc[r][c] += av[r] * bv[c];
                }
                __syncthreads();
            }
#pragma unroll
            for (int r = 0; r < 8; ++r)
#pragma unroll
                for (int c = 0; c < 16; ++c)
                    out[(size_t)(m0f + tm * 8 + r) * FOUT + n0f + tn * 16 + c] = acc[r][c];
            __syncthreads();
        }
    }
#endif
}

// ---------------------------------------------------------------------------
extern "C" void kernel_launch(void* const* d_in, const int* in_sizes, int n_in,
                              void* d_out, int out_size) {
    const float* inp = (const float*)d_in[0];  // [2, 2048, 4096]
    const float* W   = (const float*)d_in[1];  // [4096, 4096]
    const float* cw  = (const float*)d_in[2];  // [4, 1, 3, 3]
    const float* cb  = (const float*)d_in[3];  // [4]
    const float* sk  = (const float*)d_in[4];  // [4, 1, 1]
    float* out = (float*)d_out;                // [2, 2048, 4096]

    cudaFuncSetAttribute(gemm_kernel,
                         cudaFuncAttributeMaxDynamicSharedMemorySize, SMEM_BYTES);

    cvt_inp_kernel<<<8192, 256>>>((const float4*)inp);
    xform_w_kernel<<<4096, 512>>>(W, cw, cb, sk);
    gemm_kernel<<<dim3(2 * NPAIRS, 1), 256, SMEM_BYTES>>>(out);
}